// round 17
// baseline (speedup 1.0000x reference)
#include <cuda_runtime.h>
#include <cuda_bf16.h>
#include <math.h>

#define DIM   256
#define TSEQ  4096
#define BATCH 32
#define HD    64
#define MTOT  (BATCH * TSEQ)   // 131072

// ---------------- device scratch ----------------
__device__ __nv_bfloat16 g_xb[(size_t)MTOT * DIM];
__device__ __nv_bfloat16 g_q[(size_t)MTOT * DIM];
__device__ __nv_bfloat16 g_k[(size_t)MTOT * DIM];
__device__ __nv_bfloat16 g_v[(size_t)MTOT * DIM];
__device__ __nv_bfloat16 g_wh[3][DIM * DIM];
__device__ float g_acc[BATCH * DIM];
__device__ float g_fm[BATCH * DIM];
__device__ float g_hb[BATCH * DIM];

// ---------------- helpers ----------------
__device__ __forceinline__ unsigned pack_bf16x2(float a, float b) {
    unsigned short lo = __bfloat16_as_ushort(__float2bfloat16(a));
    unsigned short hi = __bfloat16_as_ushort(__float2bfloat16(b));
    return (unsigned)lo | ((unsigned)hi << 16);
}
__device__ __forceinline__ void cp_async16(unsigned dst, const void* src) {
    asm volatile("cp.async.cg.shared.global [%0], [%1], 16;" :: "r"(dst), "l"(src));
}
__device__ __forceinline__ void cp_commit() { asm volatile("cp.async.commit_group;"); }
__device__ __forceinline__ void cp_wait1() { asm volatile("cp.async.wait_group 1;"); }
__device__ __forceinline__ void cp_wait0() { asm volatile("cp.async.wait_group 0;"); }
__device__ __forceinline__ void ldsm_x4(unsigned& r0, unsigned& r1, unsigned& r2, unsigned& r3,
                                        unsigned addr) {
    asm volatile("ldmatrix.sync.aligned.m8n8.x4.shared.b16 {%0,%1,%2,%3},[%4];"
                 : "=r"(r0), "=r"(r1), "=r"(r2), "=r"(r3) : "r"(addr));
}
__device__ __forceinline__ void ldsm_x4_trans(unsigned& r0, unsigned& r1, unsigned& r2, unsigned& r3,
                                              unsigned addr) {
    asm volatile("ldmatrix.sync.aligned.m8n8.x4.trans.shared.b16 {%0,%1,%2,%3},[%4];"
                 : "=r"(r0), "=r"(r1), "=r"(r2), "=r"(r3) : "r"(addr));
}
__device__ __forceinline__ void mma_bf16(float* D, unsigned a0, unsigned a1, unsigned a2, unsigned a3,
                                         unsigned b0, unsigned b1) {
    asm volatile("mma.sync.aligned.m16n8k16.row.col.f32.bf16.bf16.f32 "
                 "{%0,%1,%2,%3},{%4,%5,%6,%7},{%8,%9},{%0,%1,%2,%3};"
                 : "+f"(D[0]), "+f"(D[1]), "+f"(D[2]), "+f"(D[3])
                 : "r"(a0), "r"(a1), "r"(a2), "r"(a3), "r"(b0), "r"(b1));
}

// ---------------- x -> bf16 ----------------
__global__ __launch_bounds__(256) void cvt_x_kernel(const float* __restrict__ x) {
    size_t i = ((size_t)blockIdx.x * 256 + threadIdx.x) * 8;
    float4 a = *(const float4*)(x + i);
    float4 b = *(const float4*)(x + i + 4);
    uint4 o;
    o.x = pack_bf16x2(a.x, a.y);
    o.y = pack_bf16x2(a.z, a.w);
    o.z = pack_bf16x2(b.x, b.y);
    o.w = pack_bf16x2(b.z, b.w);
    *(uint4*)(g_xb + i) = o;
}

// ---------------- W bf16 convert + g_acc zero ----------------
__global__ __launch_bounds__(256) void cvt_w_kernel(const float* __restrict__ Wq,
                                                    const float* __restrict__ Wk,
                                                    const float* __restrict__ Wv) {
    int gid = blockIdx.x * 256 + threadIdx.x;
    if (gid < BATCH * DIM) g_acc[gid] = 0.0f;
    int i = gid * 4;
    if (i >= 3 * DIM * DIM) return;
    int z = i >> 16;
    int o = i & 65535;
    const float* W = (z == 0) ? Wq : (z == 1) ? Wk : Wv;
    float4 v = *(const float4*)(W + o);
    uint2 ph;
    ph.x = pack_bf16x2(v.x, v.y);
    ph.y = pack_bf16x2(v.z, v.w);
    *(uint2*)(&g_wh[z][o]) = ph;
}

// ---------------- pure bf16 cp.async double-buffered GEMM ----------------
#define ASTRIDE 72
#define WSTRIDE 136
#define A_STAGE 9216            // halfwords: 128 * 72
#define W_OFF   18432           // after 2 A stages
#define W_STAGE 8704            // 64 * 136
#define GSMEM_BYTES ((2 * A_STAGE + 2 * W_STAGE) * 2)   // 71680

__device__ __forceinline__ void g_load_chunk(int c, int buf, int tid, long mbase, int nbase,
                                             const __nv_bfloat16* Whz, unsigned sb)
{
    const unsigned abase = sb + (unsigned)(buf * A_STAGE) * 2u;
    #pragma unroll
    for (int i = 0; i < 4; i++) {                 // A: 128 rows x 128B = 1024 x 16B
        int lin = tid + i * 256;
        int r = lin >> 3, c8 = lin & 7;
        cp_async16(abase + (unsigned)(r * ASTRIDE + c8 * 8) * 2u,
                   (const void*)(g_xb + (mbase + r) * DIM + c * 64 + c8 * 8));
    }
    const unsigned wbase = sb + (unsigned)(W_OFF + buf * W_STAGE) * 2u;
    #pragma unroll
    for (int i = 0; i < 4; i++) {                 // W: 64 rows x 256B = 1024 x 16B
        int lin = tid + i * 256;
        int r = lin >> 4, c8 = lin & 15;
        cp_async16(wbase + (unsigned)(r * WSTRIDE + c8 * 8) * 2u,
                   (const void*)(Whz + (c * 64 + r) * DIM + nbase + c8 * 8));
    }
    cp_commit();
}

__global__ __launch_bounds__(256, 2) void gemm_bf16_kernel(
    const float* __restrict__ bq, const float* __restrict__ bk, const float* __restrict__ bv)
{
    extern __shared__ __nv_bfloat16 sm[];
    const unsigned sb = (unsigned)__cvta_generic_to_shared(sm);

    const int z = blockIdx.x;
    const int nbase = blockIdx.y * 128;
    const long mbase = (long)blockIdx.z * 128;
    const float* bias = (z == 0) ? bq : (z == 1) ? bk : bv;
    __nv_bfloat16* C = (z == 0) ? g_q : (z == 1) ? g_k : g_v;
    const __nv_bfloat16* Whz = g_wh[z];

    const int tid = threadIdx.x;
    const int warp = tid >> 5, lane = tid & 31;
    const int wm = (warp >> 1) * 32;
    const int wn = (warp & 1) * 64;

    float acc[2][8][4];
    #pragma unroll
    for (int i = 0; i < 2; i++)
        #pragma unroll
        for (int j = 0; j < 8; j++)
            #pragma unroll
            for (int c = 0; c < 4; c++) acc[i][j][c] = 0.0f;

    g_load_chunk(0, 0, tid, mbase, nbase, Whz, sb);
    g_load_chunk(1, 1, tid, mbase, nbase, Whz, sb);

    for (int c = 0; c < 4; c++) {
        const int buf = c & 1;
        if (c < 3) cp_wait1(); else cp_wait0();
        __syncthreads();

        const unsigned ah_base = sb + (unsigned)(buf * A_STAGE) * 2u;
        const unsigned wh_base = sb + (unsigned)(W_OFF + buf * W_STAGE) * 2u;

        #pragma unroll
        for (int kk = 0; kk < 4; kk++) {
            const unsigned arow = (unsigned)((wm + (lane & 15)) * ASTRIDE + kk * 16 + (lane >> 4) * 8) * 2u;
            unsigned ah[2][4];
            ldsm_x4(ah[0][0], ah[0][1], ah[0][2], ah[0][3], ah_base + arow);
            ldsm_x4(ah[1][0], ah[1][1], ah[1][2], ah[1][3], ah_base + arow + (unsigned)(16 * ASTRIDE) * 2u);

            #pragma unroll
            for (int nt = 0; nt < 4; nt++) {
                const unsigned boff =
                    (unsigned)((kk * 16 + (lane & 15)) * WSTRIDE + wn + nt * 16 + (lane >> 4) * 8) * 2u;
                unsigned h0, h1, h2, h3;
                ldsm_x4_trans(h0, h1, h2, h3, wh_base + boff);
                #pragma unroll
                for (int mi = 0; mi < 2; mi++) {
                    mma_bf16(acc[mi][nt * 2],     ah[mi][0], ah[mi][1], ah[mi][2], ah[mi][3], h0, h1);
                    mma_bf16(acc[mi][nt * 2 + 1], ah[mi][0], ah[mi][1], ah[mi][2], ah[mi][3], h2, h3);
                }
            }
        }
        __syncthreads();
        if (c + 2 <= 3) g_load_chunk(c + 2, buf, tid, mbase, nbase, Whz, sb);
    }

    // epilogue: bf16 output
    #pragma unroll
    for (int mi = 0; mi < 2; mi++) {
        long row0 = mbase + wm + mi * 16 + (lane >> 2);
        #pragma unroll
        for (int n8 = 0; n8 < 8; n8++) {
            int col = nbase + wn + n8 * 8 + (lane & 3) * 2;
            float b0 = __ldg(&bias[col]);
            float b1 = __ldg(&bias[col + 1]);
            unsigned p0 = pack_bf16x2(acc[mi][n8][0] + b0, acc[mi][n8][1] + b1);
            unsigned p1 = pack_bf16x2(acc[mi][n8][2] + b0, acc[mi][n8][3] + b1);
            *(unsigned*)&C[row0 * DIM + col] = p0;
            *(unsigned*)&C[(row0 + 8) * DIM + col] = p1;
        }
    }
}

// ---------------- attention v9: no pooled-v tile, 6 CTA/SM ----------------
#define ASTR   68
#define NBROWS 35
#define NPROWS 24
#define STOTB  (3 * NBROWS * 8)

// phase A (half-dot); oscale folds the 1/KS v-average factor into the weights
template <int QN>
__device__ __forceinline__ void scores_half(const float* __restrict__ qrow,
                                            const float* __restrict__ kt, int lk0,
                                            float* __restrict__ aout,
                                            int l0, int lq, int Ts, int half, bool wr,
                                            float oscale)
{
    const float4* qp = (const float4*)qrow + half * 8;
    const float4* k0 = (const float4*)(kt + lk0 * ASTR) + half * 8;
    const float4* k1 = k0 + 17;
    const float4* k2 = k1 + 17;
    const float4* k3 = k2 + 17;
    float s0 = 0.f, s1 = 0.f, s2 = 0.f, s3 = 0.f;
    #pragma unroll
    for (int c = 0; c < 8; c++) {
        float4 q4 = qp[c];
        if (QN >= 2) {
            float4 qb = qp[c + 17];
            q4.x += qb.x; q4.y += qb.y; q4.z += qb.z; q4.w += qb.w;
        }
        if (QN == 4) {
            float4 qc = qp[c + 34], qd = qp[c + 51];
            q4.x += qc.x + qd.x; q4.y += qc.y + qd.y;
            q4.z += qc.z + qd.z; q4.w += qc.w + qd.w;
        }
        float4 a = k0[c], b = k1[c], d = k2[c], e = k3[c];
        s0 += q4.x * a.x + q4.y * a.y + q4.z * a.z + q4.w * a.w;
        s1 += q4.x * b.x + q4.y * b.y + q4.z * b.z + q4.w * b.w;
        s2 += q4.x * d.x + q4.y * d.y + q4.z * d.z + q4.w * d.w;
        s3 += q4.x * e.x + q4.y * e.y + q4.z * e.z + q4.w * e.w;
    }
    s0 += __shfl_xor_sync(0xffffffffu, s0, 1);
    s1 += __shfl_xor_sync(0xffffffffu, s1, 1);
    s2 += __shfl_xor_sync(0xffffffffu, s2, 1);
    s3 += __shfl_xor_sync(0xffffffffu, s3, 1);

    if (half == 0 && wr) {
        const float cs = 0.125f / (float)QN;
        bool v0 = l0 < Ts, v1 = l0 + 1 < Ts, v2 = l0 + 2 < Ts, v3 = l0 + 3 < Ts;
        s0 = v0 ? s0 * cs : 0.f;
        s1 = v1 ? s1 * cs : 0.f;
        s2 = v2 ? s2 * cs : 0.f;
        s3 = v3 ? s3 * cs : 0.f;
        float mx = fmaxf(fmaxf(s0, s1), fmaxf(s2, s3));
        float e0 = expf(s0 - mx), e1 = expf(s1 - mx);
        float e2 = expf(s2 - mx), e3 = expf(s3 - mx);
        float inv = oscale / (e0 + e1 + e2 + e3);
        aout[0] = v0 ? e0 * inv : 0.f;
        aout[1] = v1 ? e1 * inv : 0.f;
        aout[2] = v2 ? e2 * inv : 0.f;
        aout[3] = v3 ? e3 * inv : 0.f;
        float wgt = 0.f;
        if (lq < Ts)
            wgt = (float)((TSEQ * (lq + 1) + Ts - 1) / Ts - (TSEQ * lq + Ts - 1) / Ts);
        aout[4] = wgt;
    }
}

// phase B scale-1: direct base rows (weights carry no extra factor)
__device__ __forceinline__ void outrows_v(const float* __restrict__ vt,
                                          const float* __restrict__ awb,
                                          int r0, int r1, int voff, int lane,
                                          float& acc0, float& acc1)
{
    const float2* vbase = (const float2*)vt + lane;
    for (int rl = r0; rl < r1; rl++) {
        const float* e = awb + rl * 8;
        float wgt = e[4];
        if (wgt == 0.0f) continue;
        const float2* vp = vbase + (voff + (rl >> 2) * 4) * 34;
        float2 w0 = vp[0], w1 = vp[34], w2 = vp[68], w3 = vp[102];
        float a0 = e[0], a1 = e[1], a2 = e[2], a3 = e[3];
        float o0 = a0 * w0.x + a1 * w1.x + a2 * w2.x + a3 * w3.x;
        float o1 = a0 * w0.y + a1 * w1.y + a2 * w2.y + a3 * w3.y;
        float g0 = 0.5f * o0 * (1.0f + erff(o0 * 0.70710678118f));
        float g1 = 0.5f * o1 * (1.0f + erff(o1 * 0.70710678118f));
        acc0 += wgt * g0;
        acc1 += wgt * g1;
    }
}

// phase B s2/s4: on-the-fly v pooling from base rows (1/KS folded into weights)
template <int KS>
__device__ __forceinline__ void outrows_pool(const float* __restrict__ bt,
                                             const float* __restrict__ awb,
                                             int r0, int r1, int lane,
                                             float& acc0, float& acc1)
{
    const float2* vbase = (const float2*)bt + lane;
    for (int rl = r0; rl < r1; rl++) {
        const float* e = awb + rl * 8;
        float wgt = e[4];
        if (wgt == 0.0f) continue;
        const int p0r = (rl >> 2) * 4;    // first pooled row of this window
        float a0 = e[0], a1 = e[1], a2 = e[2], a3 = e[3];
        float o0 = 0.f, o1 = 0.f;
        #pragma unroll
        for (int j = 0; j < 4; j++) {
            int p = p0r + j;
            float vx = 0.f, vy = 0.f;
            #pragma unroll
            for (int r = 0; r < KS; r++) {
                int br = (KS == 2) ? (2 * p + 2 + r) : (4 * p + 1 + r);
                float2 w = vbase[br * 34];
                vx += w.x; vy += w.y;
            }
            float aj = (j == 0) ? a0 : (j == 1) ? a1 : (j == 2) ? a2 : a3;
            o0 += aj * vx;
            o1 += aj * vy;
        }
        float g0 = 0.5f * o0 * (1.0f + erff(o0 * 0.70710678118f));
        float g1 = 0.5f * o1 * (1.0f + erff(o1 * 0.70710678118f));
        acc0 += wgt * g0;
        acc1 += wgt * g1;
    }
}

__global__ __launch_bounds__(128, 6) void attn9_kernel()
{
    extern __shared__ float smf[];
    float* bq_ = smf;                       // [35][68]
    float* bk_ = bq_ + NBROWS * ASTR;
    float* bv_ = bk_ + NBROWS * ASTR;
    float* pk  = bv_ + NBROWS * ASTR;       // pooled k only [24][68]
    float* aw  = pk + NPROWS * ASTR;        // [56][8]
    float* accw = aw + 56 * 8;              // [4][64]

    const int tid = threadIdx.x;
    const int h  = blockIdx.x;
    const int bi = blockIdx.y;
    const int b  = blockIdx.z;
    const int sbase = bi * 32 - 3;
    const long gbase = (long)b * TSEQ * DIM + h * HD;

    const __nv_bfloat16* gq = g_q + gbase;
    const __nv_bfloat16* gk = g_k + gbase;
    const __nv_bfloat16* gv = g_v + gbase;

    {
        uint4 tmp[7];
        #pragma unroll
        for (int i = 0; i < 7; i++) {
            int idx = tid + i * 128;
            if (i < 6 || idx < STOTB) {
                int t = idx / (NBROWS * 8);
                int rem = idx - t * (NBROWS * 8);
                int r = rem >> 3, c8 = rem & 7;
                int o = sbase + r;
                if (o < 0) o = -o;
                if (o >= TSEQ) o = 2 * TSEQ - 2 - o;
                const __nv_bfloat16* src = (t == 0 ? gq : t == 1 ? gk : gv) + (long)o * DIM + c8 * 8;
                tmp[i] = *(const uint4*)src;
            }
        }
        #pragma unroll
        for (int i = 0; i < 7; i++) {
            int idx = tid + i * 128;
            if (i < 6 || idx < STOTB) {
                int t = idx / (NBROWS * 8);
                int rem = idx - t * (NBROWS * 8);
                int r = rem >> 3, c8 = rem & 7;
                float* dst = (t == 0 ? bq_ : t == 1 ? bk_ : bv_) + r * ASTR + c8 * 8;
                float2 f0 = __bfloat1622float2(*(__nv_bfloat162*)&tmp[i].x);
                float2 f1 = __bfloat1622float2(*(__nv_bfloat162*)&tmp[i].y);
                float2 f2 = __bfloat1622float2(*(__nv_bfloat162*)&tmp[i].z);
                float2 f3 = __bfloat1622float2(*(__nv_bfloat162*)&tmp[i].w);
                float4 lo = make_float4(f0.x, f0.y, f1.x, f1.y);
                float4 hi = make_float4(f2.x, f2.y, f3.x, f3.y);
                *(float4*)dst = lo;
                *(float4*)(dst + 4) = hi;
            }
        }
    }
    __syncthreads();

    // pooling pass: k only
    for (int idx = tid; idx < NPROWS * 16; idx += 128) {
        int r = idx >> 4;
        int c4 = (idx & 15) * 4;
        float4 o;
        if (r < 16) {
            const float4 a = *(const float4*)(bk_ + (2 * r + 2) * ASTR + c4);
            const float4 c = *(const float4*)(bk_ + (2 * r + 3) * ASTR + c4);
            o.x = 0.5f * (a.x + c.x); o.y = 0.5f * (a.y + c.y);
            o.z = 0.5f * (a.z + c.z); o.w = 0.5f * (a.w + c.w);
        } else {
            int rr = r - 16;
            const float4 a = *(const float4*)(bk_ + (4 * rr + 1) * ASTR + c4);
            const float4 c = *(const float4*)(bk_ + (4 * rr + 2) * ASTR + c4);
            const float4 d = *(const float4*)(bk_ + (4 * rr + 3) * ASTR + c4);
            const float4 e = *(const float4*)(bk_ + (4 * rr + 4) * ASTR + c4);
            o.x = 0.25f * (a.x + c.x + d.x + e.x);
            o.y = 0.25f * (a.y + c.y + d.y + e.y);
            o.z = 0.25f * (a.z + c.z + d.z + e.z);
            o.w = 0.25f * (a.w + c.w + d.w + e.w);
        }
        *(float4*)(pk + r * ASTR + c4) = o;
    }
    __syncthreads();

    const int warp = tid >> 5;
    const int lane = tid & 31;
    const int half = lane & 1;
    const int rr = lane >> 1;

    if (warp < 2) {
        int j = warp * 16 + rr;
        scores_half<1>(bq_ + (3 + j) * ASTR, bk_, 3 + (j & ~3), aw + j * 8,
                       bi * 32 + (j & ~3), bi * 32 + j, TSEQ, half, true, 1.0f);
    } else if (warp == 2) {
        int j = rr;
        scores_half<2>(bq_ + (2 * j + 2) * ASTR, pk, (j & ~3), aw + (32 + j) * 8,
                       bi * 16 + (j & ~3), bi * 16 + j, 2049, half, true, 0.5f);
    } else {
        int j = rr & 7;
        scores_half<4>(bq_ + (4 * j + 1) * ASTR, pk, 16 + (j & ~3), aw + (48 + j) * 8,
                       bi * 8 + (j & ~3), bi * 8 + j, 1025, half, rr < 8, 0.25f);
    }
    __syncthreads();

    float acc0 = 0.f, acc1 = 0.f;
    if (warp == 0)      outrows_v(bv_, aw,          0, 16, 3,  lane, acc0, acc1);
    else if (warp == 2) outrows_v(bv_, aw,         16, 32, 3,  lane, acc0, acc1);
    else if (warp == 1) outrows_pool<2>(bv_, aw + 32 * 8, 0, 16, lane, acc0, acc1);
    else                outrows_pool<4>(bv_, aw + 48 * 8, 0,  8, lane, acc0, acc1);

    *(float2*)&accw[warp * HD + 2 * lane] = make_float2(acc0, acc1);
    __syncthreads();

    if (tid < HD) {
        float s = accw[tid] + accw[HD + tid] + accw[2 * HD + tid] + accw[3 * HD + tid];
        atomicAdd(&g_acc[b * DIM + h * HD + tid], s);
    }
}

// ---------------- classifier: 3 parallel GEMV kernels ----------------
__global__ __launch_bounds__(128) void class1_kernel(const float* __restrict__ Wp,
                                                     const float* __restrict__ bp) {
    __shared__ float m[DIM];
    __shared__ float red[128];
    const int b = blockIdx.y;
    const int c0 = blockIdx.x * 32;
    const int t = threadIdx.x;
    const int col = t & 31, kp = t >> 5;
    for (int i = t; i < DIM; i += 128) m[i] = g_acc[b * DIM + i] * (1.0f / (float)TSEQ);
    __syncthreads();
    float a0 = 0.f, a1 = 0.f, a2 = 0.f, a3 = 0.f;
    const int kb = kp * 64;
    #pragma unroll 4
    for (int k = 0; k < 64; k += 4) {
        int kk = kb + k;
        a0 = fmaf(m[kk],     Wp[kk * DIM + c0 + col],       a0);
        a1 = fmaf(m[kk + 1], Wp[(kk + 1) * DIM + c0 + col], a1);
        a2 = fmaf(m[kk + 2], Wp[(kk + 2) * DIM + c0 + col], a2);
        a3 = fmaf(m[kk + 3], Wp[(kk + 3) * DIM + c0 + col], a3);
    }
    red[t] = (a0 + a1) + (a2 + a3);
    __syncthreads();
    if (kp == 0)
        g_fm[b * DIM + c0 + col] = red[col] + red[32 + col] + red[64 + col] + red[96 + col]
                                   + bp[c0 + col];
}

__global__ __launch_bounds__(128) void class2_kernel(const float* __restrict__ Wc1,
                                                     const float* __restrict__ bc1) {
    __shared__ float m[DIM];
    __shared__ float red[128];
    const int b = blockIdx.y;
    const int c0 = blockIdx.x * 32;
    const int t = threadIdx.x;
    const int col = t & 31, kp = t >> 5;
    for (int i = t; i < DIM; i += 128) m[i] = g_fm[b * DIM + i];
    __syncthreads();
    float a0 = 0.f, a1 = 0.f, a2 = 0.f, a3 = 0.f;
    const int kb = kp * 64;
    #pragma unroll 4
    for (int k = 0; k < 64; k += 4) {
        int kk = kb + k;
        a0 = fmaf(m[kk],     Wc1[kk * DIM + c0 + col],       a0);
        a1 = fmaf(m[kk + 1], Wc1[(kk + 1) * DIM + c0 + col], a1);
        a2 = fmaf(m[kk + 2], Wc1[(kk + 2) * DIM + c0 + col], a2);
        a3 = fmaf(m[kk + 3], Wc1[(kk + 3) * DIM + c0 + col], a3);
    }
    red[t] = (a0 + a1) + (a2 + a3);
    __syncthreads();
    if (kp == 0)
        g_hb[b * DIM + c0 + col] = fmaxf(red[col] + red[32 + col] + red[64 + col] + red[96 + col]
                                         + bc1[c0 + col], 0.0f);
}

__global__ __launch_bounds__(256) void class3_kernel(const float* __restrict__ Wc2,
                                                     const float* __restrict__ bc2,
                                                     float* __restrict__ out) {
    __shared__ float hsm[DIM];
    __shared__ float red[256];
    const int b = blockIdx.x;
    const int t = threadIdx.x;
    for (int i = t; i < DIM; i += 256) hsm[i] = g_hb[b * DIM + i];
    __syncthreads();
    const int col = t & 7, kp = t >> 3;
    float a = 0.f;
    if (col < 7) {
        #pragma unroll
        for (int k = 0; k < 8; k++) {
            int kk = kp * 8 + k;
            a = fmaf(hsm[kk], Wc2[kk * 7 + col], a);
        }
    }
    red[t] = a;
    __syncthreads();
    if (t < 7) {
        float s = bc2[t];
        #pragma unroll
        for (int p = 0; p < 32; p++) s += red[p * 8 + t];
        out[b * 7 + t] = s;
    }
}

// ---------------- launch ----------------
extern "C" void kernel_launch(void* const* d_in, const int* in_sizes, int n_in,
                              void* d_out, int out_size)
{
    const float* x   = (const float*)d_in[0];
    const float* Wq  = (const float*)d_in[1];
    const float* bq  = (const float*)d_in[2];
    const float* Wk  = (const float*)d_in[3];
    const float* bk  = (const float*)d_in[4];
    const float* Wv  = (const float*)d_in[5];
    const float* bv  = (const float*)d_in[6];
    const float* Wp  = (const float*)d_in[7];
    const float* bp  = (const float*)d_in[8];
    const float* Wc1 = (const float*)d_in[9];
    const float* bc1 = (const float*)d_in[10];
    const float* Wc2 = (const float*)d_in[11];
    const float* bc2 = (const float*)d_in[12];
    float* out = (float*)d_out;

    const int asmem = (3 * NBROWS * ASTR + NPROWS * ASTR + 56 * 8 + 4 * HD) * (int)sizeof(float);
    cudaFuncSetAttribute(gemm_bf16_kernel, cudaFuncAttributeMaxDynamicSharedMemorySize, GSMEM_BYTES);
    cudaFuncSetAttribute(attn9_kernel, cudaFuncAttributeMaxDynamicSharedMemorySize, asmem);

    cvt_w_kernel<<<(3 * DIM * DIM / 4 + 255) / 256, 256>>>(Wq, Wk, Wv);
    cvt_x_kernel<<<(int)(((size_t)MTOT * DIM / 8) / 256), 256>>>(x);

    gemm_bf16_kernel<<<dim3(3, 2, MTOT / 128), 256, GSMEM_BYTES>>>(bq, bk, bv);

    attn9_kernel<<<dim3(4, 129, BATCH), 128, asmem>>>();

    class1_kernel<<<dim3(8, BATCH), 128>>>(Wp, bp);
    class2_kernel<<<dim3(8, BATCH), 128>>>(Wc1, bc1);
    class3_kernel<<<BATCH, 256>>>(Wc2, bc2, out);
}